// round 10
// baseline (speedup 1.0000x reference)
#include <cuda_runtime.h>
#include <math.h>
#include <cstdint>

#define BB 2
#define NTOK 2112
#define CDIM 1024
#define NHEAD 16
#define HD 64
#define MROWS (BB*NTOK)      // 4224
#define NEGF (-1e30f)
#define EPSF 1e-5f

// ---------------- scratch (device globals: no allocation allowed) ----------------
__device__ float g_qkv[(size_t)MROWS * 3 * CDIM];          // [b*N+n][3*C]
__device__ float g_q[(size_t)BB * NHEAD * NTOK * HD];      // [b][h][n][d]
__device__ float g_k[(size_t)BB * NHEAD * NTOK * HD];
__device__ float g_v[(size_t)BB * NHEAD * NTOK * HD];
// interleaved {hi,lo} tf32-split buffers
__device__ float g_xhl[(size_t)MROWS * CDIM * 2];
__device__ float g_wqkvhl[(size_t)3 * 3 * CDIM * CDIM * 2];
__device__ float g_wprojhl[(size_t)3 * CDIM * CDIM * 2];
__device__ float g_ohl[(size_t)MROWS * CDIM * 2];

__device__ __forceinline__ int seg_of(int n) { return (n < 64) ? 0 : (n < 1088 ? 1 : 2); }

// =================================================================================
// mma.sync tf32 helpers (base sm_103 — no tcgen05 in this build path)
// =================================================================================
__device__ __forceinline__ uint32_t f2tf32(float x) {
    uint32_t r;
    asm("cvt.rna.tf32.f32 %0, %1;" : "=r"(r) : "f"(x));
    return r;
}
__device__ __forceinline__ void mma_tf32(float c[4],
                                         uint32_t a0, uint32_t a1, uint32_t a2, uint32_t a3,
                                         uint32_t b0, uint32_t b1) {
    asm volatile("mma.sync.aligned.m16n8k8.row.col.f32.tf32.tf32.f32 "
                 "{%0,%1,%2,%3}, {%4,%5,%6,%7}, {%8,%9}, {%0,%1,%2,%3};"
                 : "+f"(c[0]), "+f"(c[1]), "+f"(c[2]), "+f"(c[3])
                 : "r"(a0), "r"(a1), "r"(a2), "r"(a3), "r"(b0), "r"(b1));
}
__device__ __forceinline__ void split4(float4 v, float4& hi, float4& lo) {
    hi.x = __uint_as_float(f2tf32(v.x)); lo.x = v.x - hi.x;
    hi.y = __uint_as_float(f2tf32(v.y)); lo.y = v.y - hi.y;
    hi.z = __uint_as_float(f2tf32(v.z)); lo.z = v.z - hi.z;
    hi.w = __uint_as_float(f2tf32(v.w)); lo.w = v.w - hi.w;
}

// =================================================================================
// Prep: split fp32 array into interleaved {hi, lo} tf32 pairs (lo tf32-rounded).
// =================================================================================
__global__ __launch_bounds__(256)
void split_interleave(const float4* __restrict__ in, float4* __restrict__ out, int n4)
{
    int i = blockIdx.x * 256 + threadIdx.x;
    if (i >= n4) return;
    float4 v = in[i];
    float hx = __uint_as_float(f2tf32(v.x));
    float hy = __uint_as_float(f2tf32(v.y));
    float hz = __uint_as_float(f2tf32(v.z));
    float hw = __uint_as_float(f2tf32(v.w));
    float lx = __uint_as_float(f2tf32(v.x - hx));
    float ly = __uint_as_float(f2tf32(v.y - hy));
    float lz = __uint_as_float(f2tf32(v.z - hz));
    float lw = __uint_as_float(f2tf32(v.w - hw));
    out[2 * i]     = make_float4(hx, lx, hy, ly);
    out[2 * i + 1] = make_float4(hz, lz, hw, lw);
}

// =================================================================================
// Tensor-core GEMM on pre-split interleaved inputs (3xTF32 => fp32-level accuracy):
//   out[m][o] = sum_k A[m][k] * W[seg][o][k] + bias[seg][o]
// A, W given as interleaved {hi,lo} pairs. CTA tile 128x128, BK=32,
// 256 threads = 8 warps (4x2), warp tile 32x64. No cvt in the inner loop;
// LDS.64 fetches hi+lo of each fragment element at once.
// Row stride 72 words (72 mod 32 = 8) => conflict-free frag loads.
// =================================================================================
#define GW 72   // smem row stride in floats (32 elements * 2, no extra pad needed)

__device__ __forceinline__ int map_row(int mtile, int r, int& seg) {
    if (mtile == 0) { seg = 0; return (r < 64) ? r : (NTOK + (r - 64)); }
    int t  = mtile - 1;
    int b  = t >> 4;
    int ti = t & 15;
    seg = (ti < 8) ? 1 : 2;
    return b * NTOK + 64 + ti * 128 + r;
}

template<int ON>
__global__ __launch_bounds__(256)
void gemm_mma(const float* __restrict__ A2, const float* __restrict__ W2full,
              const float* __restrict__ bias, float* __restrict__ outp)
{
    __shared__ float As[128][GW];
    __shared__ float Ws[128][GW];

    const int t    = threadIdx.x;
    const int warp = t >> 5;
    const int lane = t & 31;
    const int wm   = warp & 3;
    const int wn   = warp >> 2;
    const int g    = lane >> 2;
    const int t4   = lane & 3;

    const int mtile = blockIdx.y;
    const int o0    = blockIdx.x * 128;
    int seg;
    (void)map_row(mtile, 0, seg);
    const float* W2 = W2full + (size_t)seg * ON * CDIM * 2;

    float acc[2][8][4];
#pragma unroll
    for (int mt = 0; mt < 2; mt++)
#pragma unroll
        for (int nt = 0; nt < 8; nt++)
#pragma unroll
            for (int c = 0; c < 4; c++) acc[mt][nt][c] = 0.f;

    for (int k0 = 0; k0 < CDIM; k0 += 32) {
        // ---- stage A and W split chunks (128 rows x 32 elems = 64 floats) ----
#pragma unroll
        for (int u = 0; u < 8; u++) {
            int f   = t + u * 256;        // 0..2047
            int row = f >> 4;
            int e2  = (f & 15) << 2;      // float offset within row (covers 2 elems)
            int sgx;
            int gr = map_row(mtile, row, sgx);
            *(float4*)&As[row][e2] =
                *(const float4*)&A2[(size_t)gr * (CDIM * 2) + k0 * 2 + e2];
            *(float4*)&Ws[row][e2] =
                *(const float4*)&W2[(size_t)(o0 + row) * (CDIM * 2) + k0 * 2 + e2];
        }
        __syncthreads();

#pragma unroll
        for (int ks = 0; ks < 4; ks++) {
            const int k8 = ks * 8;
            uint32_t ahi[2][4], alo[2][4];
#pragma unroll
            for (int mt = 0; mt < 2; mt++) {
                int r0 = wm * 32 + mt * 16 + g;
                float2 p0 = *(const float2*)&As[r0][(k8 + t4) * 2];
                float2 p1 = *(const float2*)&As[r0 + 8][(k8 + t4) * 2];
                float2 p2 = *(const float2*)&As[r0][(k8 + t4 + 4) * 2];
                float2 p3 = *(const float2*)&As[r0 + 8][(k8 + t4 + 4) * 2];
                ahi[mt][0] = __float_as_uint(p0.x); alo[mt][0] = __float_as_uint(p0.y);
                ahi[mt][1] = __float_as_uint(p1.x); alo[mt][1] = __float_as_uint(p1.y);
                ahi[mt][2] = __float_as_uint(p2.x); alo[mt][2] = __float_as_uint(p2.y);
                ahi[mt][3] = __float_as_uint(p3.x); alo[mt][3] = __float_as_uint(p3.y);
            }
            uint32_t bhi[8][2], blo[8][2];
#pragma unroll
            for (int nt = 0; nt < 8; nt++) {
                int cb = wn * 64 + nt * 8 + g;
                float2 b0 = *(const float2*)&Ws[cb][(k8 + t4) * 2];
                float2 b1 = *(const float2*)&Ws[cb][(k8 + t4 + 4) * 2];
                bhi[nt][0] = __float_as_uint(b0.x); blo[nt][0] = __float_as_uint(b0.y);
                bhi[nt][1] = __float_as_uint(b1.x); blo[nt][1] = __float_as_uint(b1.y);
            }
#pragma unroll
            for (int mt = 0; mt < 2; mt++)
#pragma unroll
                for (int nt = 0; nt < 8; nt++) {
                    mma_tf32(acc[mt][nt], ahi[mt][0], ahi[mt][1], ahi[mt][2], ahi[mt][3],
                             bhi[nt][0], bhi[nt][1]);
                    mma_tf32(acc[mt][nt], ahi[mt][0], ahi[mt][1], ahi[mt][2], ahi[mt][3],
                             blo[nt][0], blo[nt][1]);
                    mma_tf32(acc[mt][nt], alo[mt][0], alo[mt][1], alo[mt][2], alo[mt][3],
                             bhi[nt][0], bhi[nt][1]);
                }
        }
        __syncthreads();
    }

#pragma unroll
    for (int mt = 0; mt < 2; mt++) {
#pragma unroll
        for (int half = 0; half < 2; half++) {
            int r = wm * 32 + mt * 16 + g + half * 8;
            int sgx;
            int gm = map_row(mtile, r, sgx);
            const float* bp = bias + (size_t)sgx * ON + o0;
            float* op = outp + (size_t)gm * ON + o0;
#pragma unroll
            for (int nt = 0; nt < 8; nt++) {
                int cb = wn * 64 + nt * 8 + t4 * 2;
                float2 v;
                v.x = acc[mt][nt][half * 2 + 0] + bp[cb + 0];
                v.y = acc[mt][nt][half * 2 + 1] + bp[cb + 1];
                *(float2*)&op[cb] = v;
            }
        }
    }
}

// ---------------------------------------------------------------------------------
// LayerNorm (head-dim) + RoPE + scatter into [b][h][n][d] q/k/v buffers.
// ---------------------------------------------------------------------------------
__device__ __forceinline__ float block_sum_64(float v, float* red, int d)
{
    red[d] = v; __syncthreads();
    if (d < 32) red[d] += red[d + 32];
    __syncthreads();
    if (d < 32) {
        float x = red[d];
        x += __shfl_down_sync(0xffffffffu, x, 16);
        x += __shfl_down_sync(0xffffffffu, x, 8);
        x += __shfl_down_sync(0xffffffffu, x, 4);
        x += __shfl_down_sync(0xffffffffu, x, 2);
        x += __shfl_down_sync(0xffffffffu, x, 1);
        if (d == 0) red[0] = x;
    }
    __syncthreads();
    float r = red[0];
    __syncthreads();
    return r;
}

__global__ __launch_bounds__(64)
void lnrope_kernel(const float* __restrict__ qkv,
                   const int* __restrict__ pos_ids, const int* __restrict__ tpos_ids,
                   const float* __restrict__ qn_w, const float* __restrict__ qn_b,
                   const float* __restrict__ kn_w, const float* __restrict__ kn_b,
                   float* __restrict__ qout, float* __restrict__ kout, float* __restrict__ vout)
{
    const int n  = blockIdx.x;
    const int bh = blockIdx.y;
    const int b  = bh >> 4;
    const int h  = bh & 15;
    const int d  = threadIdx.x;
    const int seg = seg_of(n);

    const float* base = qkv + ((size_t)(b * NTOK + n)) * 3 * CDIM + h * HD + d;
    float qv = base[0];
    float kv = base[CDIM];
    float vv = base[2 * CDIM];

    const size_t oidx = (((size_t)bh) * NTOK + n) * HD + d;
    vout[oidx] = vv;

    __shared__ float red[64];
    __shared__ float shq[64];
    __shared__ float shk[64];

    float qmu  = block_sum_64(qv, red, d) * (1.f / 64.f);
    float qdm  = qv - qmu;
    float qvar = block_sum_64(qdm * qdm, red, d) * (1.f / 64.f);
    float lq   = qdm * rsqrtf(qvar + EPSF) * qn_w[seg * HD + d] + qn_b[seg * HD + d];

    float kmu  = block_sum_64(kv, red, d) * (1.f / 64.f);
    float kdm  = kv - kmu;
    float kvar = block_sum_64(kdm * kdm, red, d) * (1.f / 64.f);
    float lk   = kdm * rsqrtf(kvar + EPSF) * kn_w[seg * HD + d] + kn_b[seg * HD + d];

    shq[d] = lq; shk[d] = lk;
    __syncthreads();

    int pos = (n < 64) ? tpos_ids[b * 64 + n] : pos_ids[b * 2048 + (n - 64)];
    int i = d & 31;
    float inv_freq = __powf(10000.f, -(float)i * (1.f / 32.f));
    float ang = (float)pos * inv_freq;
    float s, c;
    __sincosf(ang, &s, &c);

    float qo, ko;
    if (d < 32) { qo = lq * c - shq[d + 32] * s;  ko = lk * c - shk[d + 32] * s; }
    else        { qo = lq * c + shq[d - 32] * s;  ko = lk * c + shk[d - 32] * s; }

    qout[oidx] = qo;
    kout[oidx] = ko;
}

// ---------------------------------------------------------------------------------
// Flash attention (causal) on tensor cores. BQ=BK=64, D=64. 128 threads / 4 warps.
// K/V (and Q during the prologue) staged into smem as interleaved {hi,lo} pairs:
// one LDS.64 per fragment element fetches both split terms.
// Row stride 136 words (136 mod 32 = 8) => conflict-free frag loads.
// Output written pre-split interleaved for the proj GEMM.
// ---------------------------------------------------------------------------------
#define FW 136                     // K/V/Q smem row stride (floats)
#define FPW 68                     // P smem row stride
#define FLASH_SMEM ((2 * 64 * FW + 64 * FPW) * 4)   // 87040 B

__global__ __launch_bounds__(128)
void flash_mma(const float* __restrict__ qbuf, const float* __restrict__ kbuf,
               const float* __restrict__ vbuf, float* __restrict__ ohl)
{
    extern __shared__ float smf[];
    float* Khl = smf;
    float* Vhl = Khl + 64 * FW;
    float* Ps  = Vhl + 64 * FW;

    const int qtile = blockIdx.x;
    const int bh    = blockIdx.y;
    const int b     = bh >> 4;
    const int h     = bh & 15;
    const int t    = threadIdx.x;
    const int warp = t >> 5;
    const int lane = t & 31;
    const int g    = lane >> 2;
    const int t4   = lane & 3;

    const float* qp = qbuf + (size_t)bh * NTOK * HD;
    const float* kp = kbuf + (size_t)bh * NTOK * HD;
    const float* vp = vbuf + (size_t)bh * NTOK * HD;
    const int q0 = qtile * 64;
    const int r0loc = warp * 16 + g;

    // ---- stage Q (split, interleaved) into Khl, build A-frags in registers ----
#pragma unroll
    for (int u = 0; u < 8; u++) {
        int f = t + u * 128;
        int row = f >> 4, c4 = (f & 15) << 2;
        float4 v = *(const float4*)&qp[(size_t)(q0 + row) * HD + c4];
        float4 hi, lo;
        split4(v, hi, lo);
        *(float4*)&Khl[row * FW + c4 * 2]     = make_float4(hi.x, lo.x, hi.y, lo.y);
        *(float4*)&Khl[row * FW + c4 * 2 + 4] = make_float4(hi.z, lo.z, hi.w, lo.w);
    }
    __syncthreads();

    uint32_t qhi[8][4], qlo[8][4];
#pragma unroll
    for (int k8 = 0; k8 < 8; k8++) {
        float2 p0 = *(const float2*)&Khl[r0loc * FW + (k8 * 8 + t4) * 2];
        float2 p1 = *(const float2*)&Khl[(r0loc + 8) * FW + (k8 * 8 + t4) * 2];
        float2 p2 = *(const float2*)&Khl[r0loc * FW + (k8 * 8 + t4 + 4) * 2];
        float2 p3 = *(const float2*)&Khl[(r0loc + 8) * FW + (k8 * 8 + t4 + 4) * 2];
        qhi[k8][0] = __float_as_uint(p0.x); qlo[k8][0] = __float_as_uint(p0.y);
        qhi[k8][1] = __float_as_uint(p1.x); qlo[k8][1] = __float_as_uint(p1.y);
        qhi[k8][2] = __float_as_uint(p2.x); qlo[k8][2] = __float_as_uint(p2.y);
        qhi[k8][3] = __float_as_uint(p3.x); qlo[k8][3] = __float_as_uint(p3.y);
    }

    float m0 = NEGF, m1 = NEGF, l0 = 0.f, l1 = 0.f;
    float o[8][4];
#pragma unroll
    for (int dt = 0; dt < 8; dt++)
#pragma unroll
        for (int c = 0; c < 4; c++) o[dt][c] = 0.f;

    for (int kt = 0; kt <= qtile; kt++) {
        const int k0 = kt * 64;
        __syncthreads();   // Q-frag reads / previous frag reads complete

        // ---- stage K, V split interleaved ----
#pragma unroll
        for (int u = 0; u < 8; u++) {
            int f = t + u * 128;
            int row = f >> 4, c4 = (f & 15) << 2;
            float4 kv4 = *(const float4*)&kp[(size_t)(k0 + row) * HD + c4];
            float4 vv4 = *(const float4*)&vp[(size_t)(k0 + row) * HD + c4];
            float4 hi, lo;
            split4(kv4, hi, lo);
            *(float4*)&Khl[row * FW + c4 * 2]     = make_float4(hi.x, lo.x, hi.y, lo.y);
            *(float4*)&Khl[row * FW + c4 * 2 + 4] = make_float4(hi.z, lo.z, hi.w, lo.w);
            split4(vv4, hi, lo);
            *(float4*)&Vhl[row * FW + c4 * 2]     = make_float4(hi.x, lo.x, hi.y, lo.y);
            *(float4*)&Vhl[row * FW + c4 * 2 + 4] = make_float4(hi.z, lo.z, hi.w, lo.w);
        }
        __syncthreads();

        // ---- S = Q K^T ----
        float s[8][4];
#pragma unroll
        for (int nt = 0; nt < 8; nt++)
#pragma unroll
            for (int c = 0; c < 4; c++) s[nt][c] = 0.f;

#pragma unroll
        for (int k8 = 0; k8 < 8; k8++) {
#pragma unroll
            for (int nt = 0; nt < 8; nt++) {
                int cb = (nt * 8 + g) * FW + (k8 * 8 + t4) * 2;
                float2 b0 = *(const float2*)&Khl[cb];
                float2 b1 = *(const float2*)&Khl[cb + 8];
                uint32_t bh0 = __float_as_uint(b0.x), bl0 = __float_as_uint(b0.y);
                uint32_t bh1 = __float_as_uint(b1.x), bl1 = __float_as_uint(b1.y);
                mma_tf32(s[nt], qhi[k8][0], qhi[k8][1], qhi[k8][2], qhi[k8][3], bh0, bh1);
                mma_tf32(s[nt], qhi[k8][0], qhi[k8][1], qhi[k8][2], qhi[k8][3], bl0, bl1);
                mma_tf32(s[nt], qlo[k8][0], qlo[k8][1], qlo[k8][2], qlo[k8][3], bh0, bh1);
            }
        }

        // ---- scale (+ causal mask on diagonal tile only) ----
        const int grow0 = q0 + r0loc;
        const int grow1 = grow0 + 8;
        if (kt == qtile) {
#pragma unroll
            for (int nt = 0; nt < 8; nt++) {
                int col = k0 + nt * 8 + t4 * 2;
                s[nt][0] = (col     > grow0) ? NEGF : s[nt][0] * 0.125f;
                s[nt][1] = (col + 1 > grow0) ? NEGF : s[nt][1] * 0.125f;
                s[nt][2] = (col     > grow1) ? NEGF : s[nt][2] * 0.125f;
                s[nt][3] = (col + 1 > grow1) ? NEGF : s[nt][3] * 0.125f;
            }
        } else {
#pragma unroll
            for (int nt = 0; nt < 8; nt++)
#pragma unroll
                for (int c = 0; c < 4; c++) s[nt][c] *= 0.125f;
        }

        // ---- online softmax (rows g / g+8 on a lane quad: xor 1,2) ----
        float mx0 = s[0][0], mx1 = s[0][2];
#pragma unroll
        for (int nt = 0; nt < 8; nt++) {
            mx0 = fmaxf(mx0, fmaxf(s[nt][0], s[nt][1]));
            mx1 = fmaxf(mx1, fmaxf(s[nt][2], s[nt][3]));
        }
        mx0 = fmaxf(mx0, __shfl_xor_sync(0xffffffffu, mx0, 1));
        mx0 = fmaxf(mx0, __shfl_xor_sync(0xffffffffu, mx0, 2));
        mx1 = fmaxf(mx1, __shfl_xor_sync(0xffffffffu, mx1, 1));
        mx1 = fmaxf(mx1, __shfl_xor_sync(0xffffffffu, mx1, 2));
        float mn0 = fmaxf(m0, mx0), mn1 = fmaxf(m1, mx1);
        float al0 = __expf(m0 - mn0), al1 = __expf(m1 - mn1);
        float sum0 = 0.f, sum1 = 0.f;
#pragma unroll
        for (int nt = 0; nt < 8; nt++) {
            s[nt][0] = __expf(s[nt][0] - mn0); sum0 += s[nt][0];
            s[nt][1] = __expf(s[nt][1] - mn0); sum0 += s[nt][1];
            s[nt][2] = __expf(s[nt][2] - mn1); sum1 += s[nt][2];
            s[nt][3] = __expf(s[nt][3] - mn1); sum1 += s[nt][3];
        }
        sum0 += __shfl_xor_sync(0xffffffffu, sum0, 1);
        sum0 += __shfl_xor_sync(0xffffffffu, sum0, 2);
        sum1 += __shfl_xor_sync(0xffffffffu, sum1, 1);
        sum1 += __shfl_xor_sync(0xffffffffu, sum1, 2);
        l0 = l0 * al0 + sum0;  m0 = mn0;
        l1 = l1 * al1 + sum1;  m1 = mn1;
#pragma unroll
        for (int dt = 0; dt < 8; dt++) {
            o[dt][0] *= al0; o[dt][1] *= al0;
            o[dt][2] *= al1; o[dt][3] *= al1;
        }

        // ---- P -> own smem strip (only this warp reads it back) ----
#pragma unroll
        for (int nt = 0; nt < 8; nt++) {
            *(float2*)&Ps[r0loc * FPW + nt * 8 + t4 * 2]       = make_float2(s[nt][0], s[nt][1]);
            *(float2*)&Ps[(r0loc + 8) * FPW + nt * 8 + t4 * 2] = make_float2(s[nt][2], s[nt][3]);
        }
        __syncwarp();

        // ---- O += P V ----
#pragma unroll
        for (int kk = 0; kk < 8; kk++) {
            float a0 = Ps[r0loc * FPW + kk * 8 + t4];
            float a1 = Ps[(r0loc + 8) * FPW + kk * 8 + t4];
            float a2 = Ps[r0loc * FPW + kk * 8 + t4 + 4];
            float a3 = Ps[(r0loc + 8) * FPW + kk * 8 + t4 + 4];
            float h0 = __uint_as_float(f2tf32(a0));
            float h1 = __uint_as_float(f2tf32(a1));
            float h2 = __uint_as_float(f2tf32(a2));
            float h3 = __uint_as_float(f2tf32(a3));
            uint32_t phi[4] = { __float_as_uint(h0), __float_as_uint(h1),
                                __float_as_uint(h2), __float_as_uint(h3) };
            uint32_t plo[4] = { f2tf32(a0 - h0), f2tf32(a1 - h1),
                                f2tf32(a2 - h2), f2tf32(a3 - h3) };
#pragma unroll
            for (int dt = 0; dt < 8; dt++) {
                int i0 = (kk * 8 + t4) * FW + (dt * 8 + g) * 2;
                int i1 = (kk * 8 + t4 + 4) * FW + (dt * 8 + g) * 2;
                float2 v0 = *(const float2*)&Vhl[i0];
                float2 v1 = *(const float2*)&Vhl[i1];
                uint32_t bh0 = __float_as_uint(v0.x), bl0 = __float_as_uint(v0.y);
                uint32_t bh1 = __float_as_uint(v1.x), bl1 = __float_as_uint(v1.y);
                mma_tf32(o[dt], phi[0], phi[1], phi[2], phi[3], bh0, bh1);
                mma_tf32(o[dt], phi[0], phi[1], phi[2], phi[3], bl0, bl1);
                mma_tf32(o[dt], plo[0], plo[1], plo[2], plo[3], bh0, bh1);
            }
        }
    }

    // ---- epilogue: normalize, split, write interleaved [b][n][h*64+d][2] ----
    const float inv0 = 1.f / l0;
    const float inv1 = 1.f / l1;
    const size_t row0 = (size_t)b * NTOK + q0 + r0loc;
    const size_t row1 = row0 + 8;
#pragma unroll
    for (int dt = 0; dt < 8; dt++) {
        int col = h * HD + dt * 8 + t4 * 2;
        float v0 = o[dt][0] * inv0, v1 = o[dt][1] * inv0;
        float v2 = o[dt][2] * inv1, v3 = o[dt][3] * inv1;
        float h0 = __uint_as_float(f2tf32(v0));
        float h1 = __uint_as_float(f2tf32(v1));
        float h2 = __uint_as_float(f2tf32(v2));
        float h3 = __uint_as_float(f2tf32(v3));
        *(float4*)&ohl[(row0 * CDIM + col) * 2] =
            make_float4(h0, __uint_as_float(f2tf32(v0 - h0)), h1, __uint_as_float(f2tf32(v1 - h1)));
        *(float4*)&ohl[(row1 * CDIM + col) * 2] =
            make_float4(h2, __uint_as_float(f2tf32(v2 - h2)), h3, __uint_as_float(f2tf32(v3 - h3)));
    }
}

// ---------------------------------------------------------------------------------
extern "C" void kernel_launch(void* const* d_in, const int* in_sizes, int n_in,
                              void* d_out, int out_size)
{
    const float* x        = (const float*)d_in[0];
    const int*   pos_ids  = (const int*)d_in[1];
    const int*   tpos_ids = (const int*)d_in[2];
    const float* qkv_w  = (const float*)d_in[7];
    const float* qkv_b  = (const float*)d_in[8];
    const float* qn_w   = (const float*)d_in[9];
    const float* qn_b   = (const float*)d_in[10];
    const float* kn_w   = (const float*)d_in[11];
    const float* kn_b   = (const float*)d_in[12];
    const float* proj_w = (const float*)d_in[13];
    const float* proj_b = (const float*)d_in[14];
    float* out = (float*)d_out;

    float *p_qkv, *p_q, *p_k, *p_v;
    float *p_xhl, *p_wqkvhl, *p_wprojhl, *p_ohl;
    cudaGetSymbolAddress((void**)&p_qkv,     g_qkv);
    cudaGetSymbolAddress((void**)&p_q,       g_q);
    cudaGetSymbolAddress((void**)&p_k,       g_k);
    cudaGetSymbolAddress((void**)&p_v,       g_v);
    cudaGetSymbolAddress((void**)&p_xhl,     g_xhl);
    cudaGetSymbolAddress((void**)&p_wqkvhl,  g_wqkvhl);
    cudaGetSymbolAddress((void**)&p_wprojhl, g_wprojhl);
    cudaGetSymbolAddress((void**)&p_ohl,     g_ohl);

    cudaFuncSetAttribute(flash_mma, cudaFuncAttributeMaxDynamicSharedMemorySize, FLASH_SMEM);

    // 0) pre-split weights and x into interleaved {hi,lo} tf32 pairs
    {
        int n4;
        n4 = (3 * 3 * CDIM * CDIM) / 4;
        split_interleave<<<(n4 + 255) / 256, 256>>>((const float4*)qkv_w, (float4*)p_wqkvhl, n4);
        n4 = (3 * CDIM * CDIM) / 4;
        split_interleave<<<(n4 + 255) / 256, 256>>>((const float4*)proj_w, (float4*)p_wprojhl, n4);
        n4 = (MROWS * CDIM) / 4;
        split_interleave<<<(n4 + 255) / 256, 256>>>((const float4*)x, (float4*)p_xhl, n4);
    }

    // 1) QKV projection (pre-split inputs). 33 M-tiles.
    gemm_mma<3 * CDIM><<<dim3(3 * CDIM / 128, 33), 256>>>(p_xhl, p_wqkvhl, qkv_b, p_qkv);

    // 2) LN(q,k) + RoPE + scatter to [b][h][n][d]
    lnrope_kernel<<<dim3(NTOK, BB * NHEAD), 64>>>(p_qkv, pos_ids, tpos_ids,
                                                  qn_w, qn_b, kn_w, kn_b,
                                                  p_q, p_k, p_v);

    // 3) causal flash attention (tensor cores) -> pre-split interleaved o
    flash_mma<<<dim3(NTOK / 64, BB * NHEAD), 128, FLASH_SMEM>>>(p_q, p_k, p_v, p_ohl);

    // 4) output projection (pre-split inputs)
    gemm_mma<CDIM><<<dim3(CDIM / 128, 33), 256>>>(p_ohl, p_wprojhl, proj_b, out);
}

// round 11
// speedup vs baseline: 1.3723x; 1.3723x over previous
#include <cuda_runtime.h>
#include <math.h>
#include <cstdint>

#define BB 2
#define NTOK 2112
#define CDIM 1024
#define NHEAD 16
#define HD 64
#define MROWS (BB*NTOK)      // 4224
#define NEGF (-1e30f)
#define EPSF 1e-5f

// ---------------- scratch (device globals: no allocation allowed) ----------------
__device__ float g_qkv[(size_t)MROWS * 3 * CDIM];          // [b*N+n][3*C]
__device__ float g_q[(size_t)BB * NHEAD * NTOK * HD];      // [b][h][n][d]
__device__ float g_k[(size_t)BB * NHEAD * NTOK * HD];
__device__ float g_v[(size_t)BB * NHEAD * NTOK * HD];
__device__ float g_o[(size_t)MROWS * CDIM];                // [b*N+n][c]

__device__ __forceinline__ int seg_of(int n) { return (n < 64) ? 0 : (n < 1088 ? 1 : 2); }

// =================================================================================
// mma.sync tf32 helpers (base sm_103 — no tcgen05 in this build path)
// =================================================================================
__device__ __forceinline__ uint32_t f2tf32(float x) {
    uint32_t r;
    asm("cvt.rna.tf32.f32 %0, %1;" : "=r"(r) : "f"(x));
    return r;
}
__device__ __forceinline__ void mma_tf32(float c[4],
                                         uint32_t a0, uint32_t a1, uint32_t a2, uint32_t a3,
                                         uint32_t b0, uint32_t b1) {
    asm volatile("mma.sync.aligned.m16n8k8.row.col.f32.tf32.tf32.f32 "
                 "{%0,%1,%2,%3}, {%4,%5,%6,%7}, {%8,%9}, {%0,%1,%2,%3};"
                 : "+f"(c[0]), "+f"(c[1]), "+f"(c[2]), "+f"(c[3])
                 : "r"(a0), "r"(a1), "r"(a2), "r"(a3), "r"(b0), "r"(b1));
}
__device__ __forceinline__ void split4(float4 v, float4& hi, float4& lo) {
    hi.x = __uint_as_float(f2tf32(v.x)); lo.x = v.x - hi.x;
    hi.y = __uint_as_float(f2tf32(v.y)); lo.y = v.y - hi.y;
    hi.z = __uint_as_float(f2tf32(v.z)); lo.z = v.z - hi.z;
    hi.w = __uint_as_float(f2tf32(v.w)); lo.w = v.w - hi.w;
}
__device__ __forceinline__ void cp16(uint32_t smem_dst, const void* gptr) {
    asm volatile("cp.async.cg.shared.global [%0], [%1], 16;"
                 :: "r"(smem_dst), "l"(gptr));
}

// =================================================================================
// Tensor-core GEMM (3xTF32 split => fp32-level accuracy):
//   out[m][o] = sum_k A[m][k] * W[seg][o][k] + bias[seg][o]
// CTA tile 128x128, BK=32, 256 threads = 8 warps (4x2), warp tile 32x64.
// cp.async double-buffered staging; __launch_bounds__(256,2) pins 2 CTAs/SM
// (R10 lesson: register growth past 128 halves residency and loses more than
//  any issue-slot saving).
// =================================================================================
#define GPAD 36
#define NCHUNK (CDIM / 32)      // 32

__device__ __forceinline__ int map_row(int mtile, int r, int& seg) {
    if (mtile == 0) { seg = 0; return (r < 64) ? r : (NTOK + (r - 64)); }
    int t  = mtile - 1;
    int b  = t >> 4;
    int ti = t & 15;
    seg = (ti < 8) ? 1 : 2;
    return b * NTOK + 64 + ti * 128 + r;
}

template<int ON>
__global__ __launch_bounds__(256, 2)
void gemm_mma(const float* __restrict__ A, const float* __restrict__ Wt,
              const float* __restrict__ bias, float* __restrict__ outp)
{
    __shared__ float As[2][128][GPAD];
    __shared__ float Ws[2][128][GPAD];

    const int t    = threadIdx.x;
    const int warp = t >> 5;
    const int lane = t & 31;
    const int wm   = warp & 3;
    const int wn   = warp >> 2;
    const int g    = lane >> 2;
    const int t4   = lane & 3;

    const int mtile = blockIdx.y;
    const int o0    = blockIdx.x * 128;
    int seg;
    (void)map_row(mtile, 0, seg);
    const float* W = Wt + (size_t)seg * ON * CDIM;

    // per-thread staging coordinates (4 rows each for A and W)
    const int srow = t >> 3;            // 0..31 base row
    const int sc4  = (t & 7) << 2;      // k-offset within chunk
    int sgx;
    const float* aload[4];
    const float* wload[4];
    uint32_t sa[2][4], sw[2][4];
#pragma unroll
    for (int u = 0; u < 4; u++) {
        int row = srow + u * 32;
        aload[u] = &A[(size_t)map_row(mtile, row, sgx) * CDIM + sc4];
        wload[u] = &W[(size_t)(o0 + row) * CDIM + sc4];
#pragma unroll
        for (int bsel = 0; bsel < 2; bsel++) {
            sa[bsel][u] = (uint32_t)__cvta_generic_to_shared(&As[bsel][row][sc4]);
            sw[bsel][u] = (uint32_t)__cvta_generic_to_shared(&Ws[bsel][row][sc4]);
        }
    }

    float acc[2][8][4];
#pragma unroll
    for (int mt = 0; mt < 2; mt++)
#pragma unroll
        for (int nt = 0; nt < 8; nt++)
#pragma unroll
            for (int c = 0; c < 4; c++) acc[mt][nt][c] = 0.f;

    // prefetch chunk 0
#pragma unroll
    for (int u = 0; u < 4; u++) {
        cp16(sa[0][u], aload[u]);
        cp16(sw[0][u], wload[u]);
    }
    asm volatile("cp.async.commit_group;");

    for (int c = 0; c < NCHUNK; c++) {
        const int buf = c & 1;
        if (c + 1 < NCHUNK) {
            const int nb = (c + 1) & 1;
            const int koff = (c + 1) * 32;
#pragma unroll
            for (int u = 0; u < 4; u++) {
                cp16(sa[nb][u], aload[u] + koff);
                cp16(sw[nb][u], wload[u] + koff);
            }
            asm volatile("cp.async.commit_group;");
            asm volatile("cp.async.wait_group 1;");
        } else {
            asm volatile("cp.async.wait_group 0;");
        }
        __syncthreads();

#pragma unroll
        for (int ks = 0; ks < 4; ks++) {
            const int k8 = ks * 8;
            uint32_t ahi[2][4], alo[2][4];
#pragma unroll
            for (int mt = 0; mt < 2; mt++) {
                int r0 = wm * 32 + mt * 16 + g;
                float a0 = As[buf][r0][k8 + t4];
                float a1 = As[buf][r0 + 8][k8 + t4];
                float a2 = As[buf][r0][k8 + t4 + 4];
                float a3 = As[buf][r0 + 8][k8 + t4 + 4];
                float h0 = __uint_as_float(f2tf32(a0));
                float h1 = __uint_as_float(f2tf32(a1));
                float h2 = __uint_as_float(f2tf32(a2));
                float h3 = __uint_as_float(f2tf32(a3));
                ahi[mt][0] = __float_as_uint(h0); alo[mt][0] = f2tf32(a0 - h0);
                ahi[mt][1] = __float_as_uint(h1); alo[mt][1] = f2tf32(a1 - h1);
                ahi[mt][2] = __float_as_uint(h2); alo[mt][2] = f2tf32(a2 - h2);
                ahi[mt][3] = __float_as_uint(h3); alo[mt][3] = f2tf32(a3 - h3);
            }
            uint32_t bhi[8][2], blo[8][2];
#pragma unroll
            for (int nt = 0; nt < 8; nt++) {
                int cb = wn * 64 + nt * 8 + g;
                float b0 = Ws[buf][cb][k8 + t4];
                float b1 = Ws[buf][cb][k8 + t4 + 4];
                float h0 = __uint_as_float(f2tf32(b0));
                float h1 = __uint_as_float(f2tf32(b1));
                bhi[nt][0] = __float_as_uint(h0); blo[nt][0] = f2tf32(b0 - h0);
                bhi[nt][1] = __float_as_uint(h1); blo[nt][1] = f2tf32(b1 - h1);
            }
#pragma unroll
            for (int mt = 0; mt < 2; mt++)
#pragma unroll
                for (int nt = 0; nt < 8; nt++) {
                    mma_tf32(acc[mt][nt], ahi[mt][0], ahi[mt][1], ahi[mt][2], ahi[mt][3],
                             bhi[nt][0], bhi[nt][1]);
                    mma_tf32(acc[mt][nt], ahi[mt][0], ahi[mt][1], ahi[mt][2], ahi[mt][3],
                             blo[nt][0], blo[nt][1]);
                    mma_tf32(acc[mt][nt], alo[mt][0], alo[mt][1], alo[mt][2], alo[mt][3],
                             bhi[nt][0], bhi[nt][1]);
                }
        }
        __syncthreads();
    }

#pragma unroll
    for (int mt = 0; mt < 2; mt++) {
#pragma unroll
        for (int half = 0; half < 2; half++) {
            int r = wm * 32 + mt * 16 + g + half * 8;
            int sgx2;
            int gm = map_row(mtile, r, sgx2);
            const float* bp = bias + (size_t)sgx2 * ON + o0;
            float* op = outp + (size_t)gm * ON + o0;
#pragma unroll
            for (int nt = 0; nt < 8; nt++) {
                int cb = wn * 64 + nt * 8 + t4 * 2;
                float2 v;
                v.x = acc[mt][nt][half * 2 + 0] + bp[cb + 0];
                v.y = acc[mt][nt][half * 2 + 1] + bp[cb + 1];
                *(float2*)&op[cb] = v;
            }
        }
    }
}

// ---------------------------------------------------------------------------------
// LayerNorm (head-dim) + RoPE + scatter into [b][h][n][d] q/k/v buffers.
// ---------------------------------------------------------------------------------
__device__ __forceinline__ float block_sum_64(float v, float* red, int d)
{
    red[d] = v; __syncthreads();
    if (d < 32) red[d] += red[d + 32];
    __syncthreads();
    if (d < 32) {
        float x = red[d];
        x += __shfl_down_sync(0xffffffffu, x, 16);
        x += __shfl_down_sync(0xffffffffu, x, 8);
        x += __shfl_down_sync(0xffffffffu, x, 4);
        x += __shfl_down_sync(0xffffffffu, x, 2);
        x += __shfl_down_sync(0xffffffffu, x, 1);
        if (d == 0) red[0] = x;
    }
    __syncthreads();
    float r = red[0];
    __syncthreads();
    return r;
}

__global__ __launch_bounds__(64)
void lnrope_kernel(const float* __restrict__ qkv,
                   const int* __restrict__ pos_ids, const int* __restrict__ tpos_ids,
                   const float* __restrict__ qn_w, const float* __restrict__ qn_b,
                   const float* __restrict__ kn_w, const float* __restrict__ kn_b,
                   float* __restrict__ qout, float* __restrict__ kout, float* __restrict__ vout)
{
    const int n  = blockIdx.x;
    const int bh = blockIdx.y;
    const int b  = bh >> 4;
    const int h  = bh & 15;
    const int d  = threadIdx.x;
    const int seg = seg_of(n);

    const float* base = qkv + ((size_t)(b * NTOK + n)) * 3 * CDIM + h * HD + d;
    float qv = base[0];
    float kv = base[CDIM];
    float vv = base[2 * CDIM];

    const size_t oidx = (((size_t)bh) * NTOK + n) * HD + d;
    vout[oidx] = vv;

    __shared__ float red[64];
    __shared__ float shq[64];
    __shared__ float shk[64];

    float qmu  = block_sum_64(qv, red, d) * (1.f / 64.f);
    float qdm  = qv - qmu;
    float qvar = block_sum_64(qdm * qdm, red, d) * (1.f / 64.f);
    float lq   = qdm * rsqrtf(qvar + EPSF) * qn_w[seg * HD + d] + qn_b[seg * HD + d];

    float kmu  = block_sum_64(kv, red, d) * (1.f / 64.f);
    float kdm  = kv - kmu;
    float kvar = block_sum_64(kdm * kdm, red, d) * (1.f / 64.f);
    float lk   = kdm * rsqrtf(kvar + EPSF) * kn_w[seg * HD + d] + kn_b[seg * HD + d];

    shq[d] = lq; shk[d] = lk;
    __syncthreads();

    int pos = (n < 64) ? tpos_ids[b * 64 + n] : pos_ids[b * 2048 + (n - 64)];
    int i = d & 31;
    float inv_freq = __powf(10000.f, -(float)i * (1.f / 32.f));
    float ang = (float)pos * inv_freq;
    float s, c;
    __sincosf(ang, &s, &c);

    float qo, ko;
    if (d < 32) { qo = lq * c - shq[d + 32] * s;  ko = lk * c - shk[d + 32] * s; }
    else        { qo = lq * c + shq[d - 32] * s;  ko = lk * c + shk[d - 32] * s; }

    qout[oidx] = qo;
    kout[oidx] = ko;
}

// ---------------------------------------------------------------------------------
// Flash attention (causal) on tensor cores. BQ=BK=64, D=64. 128 threads / 4 warps.
// Warp w owns m16 row strip w*16..w*16+15.
//   S = Q K^T : A-frags = pre-split Q (registers), B-frags = Kh/Kl smem [seq][d].
//   P V       : A-frags = P via smem (own strip, __syncwarp), B-frags read V
//               directly from [seq][d] layout (row.col B[n][k] == V[k][n]).
// 3xTF32 split on both GEMMs => fp32-level accuracy.
// ---------------------------------------------------------------------------------
#define FP 68
#define FLASH_SMEM (5 * 64 * FP * 4)   // Kh, Kl, Vh, Vl, Ps = 87040 B

__global__ __launch_bounds__(128)
void flash_mma(const float* __restrict__ qbuf, const float* __restrict__ kbuf,
               const float* __restrict__ vbuf, float* __restrict__ obuf)
{
    extern __shared__ float smf[];
    float* Kh = smf;
    float* Kl = Kh + 64 * FP;
    float* Vh = Kl + 64 * FP;
    float* Vl = Vh + 64 * FP;
    float* Ps = Vl + 64 * FP;

    const int qtile = blockIdx.x;
    const int bh    = blockIdx.y;
    const int b     = bh >> 4;
    const int h     = bh & 15;
    const int t    = threadIdx.x;
    const int warp = t >> 5;
    const int lane = t & 31;
    const int g    = lane >> 2;
    const int t4   = lane & 3;

    const float* qp = qbuf + (size_t)bh * NTOK * HD;
    const float* kp = kbuf + (size_t)bh * NTOK * HD;
    const float* vp = vbuf + (size_t)bh * NTOK * HD;
    const int q0 = qtile * 64;
    const int r0loc = warp * 16 + g;

    // ---- stage Q tile into Ps, then pre-split A-frags into registers ----
#pragma unroll
    for (int u = 0; u < 8; u++) {
        int f = t + u * 128;
        int row = f >> 4, c4 = (f & 15) << 2;
        *(float4*)&Ps[row * FP + c4] = *(const float4*)&qp[(size_t)(q0 + row) * HD + c4];
    }
    __syncthreads();

    uint32_t qhi[8][4], qlo[8][4];
#pragma unroll
    for (int k8 = 0; k8 < 8; k8++) {
        float a0 = Ps[r0loc * FP + k8 * 8 + t4];
        float a1 = Ps[(r0loc + 8) * FP + k8 * 8 + t4];
        float a2 = Ps[r0loc * FP + k8 * 8 + t4 + 4];
        float a3 = Ps[(r0loc + 8) * FP + k8 * 8 + t4 + 4];
        float h0 = __uint_as_float(f2tf32(a0));
        float h1 = __uint_as_float(f2tf32(a1));
        float h2 = __uint_as_float(f2tf32(a2));
        float h3 = __uint_as_float(f2tf32(a3));
        qhi[k8][0] = __float_as_uint(h0); qlo[k8][0] = f2tf32(a0 - h0);
        qhi[k8][1] = __float_as_uint(h1); qlo[k8][1] = f2tf32(a1 - h1);
        qhi[k8][2] = __float_as_uint(h2); qlo[k8][2] = f2tf32(a2 - h2);
        qhi[k8][3] = __float_as_uint(h3); qlo[k8][3] = f2tf32(a3 - h3);
    }

    float m0 = NEGF, m1 = NEGF, l0 = 0.f, l1 = 0.f;
    float o[8][4];
#pragma unroll
    for (int dt = 0; dt < 8; dt++)
#pragma unroll
        for (int c = 0; c < 4; c++) o[dt][c] = 0.f;

    for (int kt = 0; kt <= qtile; kt++) {
        const int k0 = kt * 64;
        __syncthreads();

        // ---- stage K, V hi/lo split, layout [seq][d] ----
#pragma unroll
        for (int u = 0; u < 8; u++) {
            int f = t + u * 128;
            int row = f >> 4, c4 = (f & 15) << 2;
            float4 kv4 = *(const float4*)&kp[(size_t)(k0 + row) * HD + c4];
            float4 vv4 = *(const float4*)&vp[(size_t)(k0 + row) * HD + c4];
            float4 hi, lo;
            split4(kv4, hi, lo);
            *(float4*)&Kh[row * FP + c4] = hi;
            *(float4*)&Kl[row * FP + c4] = lo;
            split4(vv4, hi, lo);
            *(float4*)&Vh[row * FP + c4] = hi;
            *(float4*)&Vl[row * FP + c4] = lo;
        }
        __syncthreads();

        // ---- S = Q K^T ----
        float s[8][4];
#pragma unroll
        for (int nt = 0; nt < 8; nt++)
#pragma unroll
            for (int c = 0; c < 4; c++) s[nt][c] = 0.f;

#pragma unroll
        for (int k8 = 0; k8 < 8; k8++) {
#pragma unroll
            for (int nt = 0; nt < 8; nt++) {
                int cb = (nt * 8 + g) * FP + k8 * 8 + t4;
                uint32_t bh0 = __float_as_uint(Kh[cb]);
                uint32_t bh1 = __float_as_uint(Kh[cb + 4]);
                uint32_t bl0 = __float_as_uint(Kl[cb]);
                uint32_t bl1 = __float_as_uint(Kl[cb + 4]);
                mma_tf32(s[nt], qhi[k8][0], qhi[k8][1], qhi[k8][2], qhi[k8][3], bh0, bh1);
                mma_tf32(s[nt], qhi[k8][0], qhi[k8][1], qhi[k8][2], qhi[k8][3], bl0, bl1);
                mma_tf32(s[nt], qlo[k8][0], qlo[k8][1], qlo[k8][2], qlo[k8][3], bh0, bh1);
            }
        }

        // ---- scale (+ causal mask on diagonal tile only) ----
        const int grow0 = q0 + r0loc;
        const int grow1 = grow0 + 8;
        if (kt == qtile) {
#pragma unroll
            for (int nt = 0; nt < 8; nt++) {
                int col = k0 + nt * 8 + t4 * 2;
                s[nt][0] = (col     > grow0) ? NEGF : s[nt][0] * 0.125f;
                s[nt][1] = (col + 1 > grow0) ? NEGF : s[nt][1] * 0.125f;
                s[nt][2] = (col     > grow1) ? NEGF : s[nt][2] * 0.125f;
                s[nt][3] = (col + 1 > grow1) ? NEGF : s[nt][3] * 0.125f;
            }
        } else {
#pragma unroll
            for (int nt = 0; nt < 8; nt++)
#pragma unroll
                for (int c = 0; c < 4; c++) s[nt][c] *= 0.125f;
        }

        // ---- online softmax (rows g / g+8 on a lane quad: xor 1,2) ----
        float mx0 = s[0][0], mx1 = s[0][2];
#pragma unroll
        for (int nt = 0; nt < 8; nt++) {
            mx0 = fmaxf(mx0, fmaxf(s[nt][0], s[nt][1]));
            mx1 = fmaxf(mx1, fmaxf(s[nt][2], s[nt][3]));
        }
        mx0 = fmaxf(mx0, __shfl_xor_sync(0xffffffffu, mx0, 1));
        mx0 = fmaxf(mx0, __shfl_xor_sync(0xffffffffu, mx0, 2));
        mx1 = fmaxf(mx1, __shfl_xor_sync(0xffffffffu, mx1, 1));
        mx1 = fmaxf(mx1, __shfl_xor_sync(0xffffffffu, mx1, 2));
        float mn0 = fmaxf(m0, mx0), mn1 = fmaxf(m1, mx1);
        float al0 = __expf(m0 - mn0), al1 = __expf(m1 - mn1);
        float sum0 = 0.f, sum1 = 0.f;
#pragma unroll
        for (int nt = 0; nt < 8; nt++) {
            s[nt][0] = __expf(s[nt][0] - mn0); sum0 += s[nt][0];
            s[nt][1] = __expf(s[nt][1] - mn0); sum0 += s[nt][1];
            s[nt][2] = __expf(s[nt][2] - mn1); sum1 += s[nt][2];
            s[nt][3] = __expf(s[nt][3] - mn1); sum1 += s[nt][3];
        }
        sum0 += __shfl_xor_sync(0xffffffffu, sum0, 1);
        sum0 += __shfl_xor_sync(0xffffffffu, sum0, 2);
        sum1 += __shfl_xor_sync(0xffffffffu, sum1, 1);
        sum1 += __shfl_xor_sync(0xffffffffu, sum1, 2);
        l0 = l0 * al0 + sum0;  m0 = mn0;
        l1 = l1 * al1 + sum1;  m1 = mn1;
#pragma unroll
        for (int dt = 0; dt < 8; dt++) {
            o[dt][0] *= al0; o[dt][1] *= al0;
            o[dt][2] *= al1; o[dt][3] *= al1;
        }

        // ---- P -> own smem strip (only this warp reads it back) ----
#pragma unroll
        for (int nt = 0; nt < 8; nt++) {
            *(float2*)&Ps[r0loc * FP + nt * 8 + t4 * 2]       = make_float2(s[nt][0], s[nt][1]);
            *(float2*)&Ps[(r0loc + 8) * FP + nt * 8 + t4 * 2] = make_float2(s[nt][2], s[nt][3]);
        }
        __syncwarp();

        // ---- O += P V ----
#pragma unroll
        for (int kk = 0; kk < 8; kk++) {
            float a0 = Ps[r0loc * FP + kk * 8 + t4];
            float a1 = Ps[(r0loc + 8) * FP + kk * 8 + t4];
            float a2 = Ps[r0loc * FP + kk * 8 + t4 + 4];
            float a3 = Ps[(r0loc + 8) * FP + kk * 8 + t4 + 4];
            float h0 = __uint_as_float(f2tf32(a0));
            float h1 = __uint_as_float(f2tf32(a1));
            float h2 = __uint_as_float(f2tf32(a2));
            float h3 = __uint_as_float(f2tf32(a3));
            uint32_t phi[4] = { __float_as_uint(h0), __float_as_uint(h1),
                                __float_as_uint(h2), __float_as_uint(h3) };
            uint32_t plo[4] = { f2tf32(a0 - h0), f2tf32(a1 - h1),
                                f2tf32(a2 - h2), f2tf32(a3 - h3) };
#pragma unroll
            for (int dt = 0; dt < 8; dt++) {
                int i0 = (kk * 8 + t4) * FP + dt * 8 + g;
                int i1 = (kk * 8 + t4 + 4) * FP + dt * 8 + g;
                uint32_t bh0 = __float_as_uint(Vh[i0]);
                uint32_t bh1 = __float_as_uint(Vh[i1]);
                uint32_t bl0 = __float_as_uint(Vl[i0]);
                uint32_t bl1 = __float_as_uint(Vl[i1]);
                mma_tf32(o[dt], phi[0], phi[1], phi[2], phi[3], bh0, bh1);
                mma_tf32(o[dt], phi[0], phi[1], phi[2], phi[3], bl0, bl1);
                mma_tf32(o[dt], plo[0], plo[1], plo[2], plo[3], bh0, bh1);
            }
        }
    }

    // ---- epilogue: normalize, write [b][n][h*64+d] ----
    const float inv0 = 1.f / l0;
    const float inv1 = 1.f / l1;
    const size_t row0 = (size_t)b * NTOK + q0 + r0loc;
    const size_t row1 = row0 + 8;
#pragma unroll
    for (int dt = 0; dt < 8; dt++) {
        int col = h * HD + dt * 8 + t4 * 2;
        *(float2*)&obuf[row0 * CDIM + col] = make_float2(o[dt][0] * inv0, o[dt][1] * inv0);
        *(float2*)&obuf[row1 * CDIM + col] = make_float2(o[dt][2] * inv1, o[dt][3] * inv1);
    }
}

// ---------------------------------------------------------------------------------
extern "C" void kernel_launch(void* const* d_in, const int* in_sizes, int n_in,
                              void* d_out, int out_size)
{
    const float* x        = (const float*)d_in[0];
    const int*   pos_ids  = (const int*)d_in[1];
    const int*   tpos_ids = (const int*)d_in[2];
    const float* qkv_w  = (const float*)d_in[7];
    const float* qkv_b  = (const float*)d_in[8];
    const float* qn_w   = (const float*)d_in[9];
    const float* qn_b   = (const float*)d_in[10];
    const float* kn_w   = (const float*)d_in[11];
    const float* kn_b   = (const float*)d_in[12];
    const float* proj_w = (const float*)d_in[13];
    const float* proj_b = (const float*)d_in[14];
    float* out = (float*)d_out;

    float *p_qkv, *p_q, *p_k, *p_v, *p_o;
    cudaGetSymbolAddress((void**)&p_qkv, g_qkv);
    cudaGetSymbolAddress((void**)&p_q,   g_q);
    cudaGetSymbolAddress((void**)&p_k,   g_k);
    cudaGetSymbolAddress((void**)&p_v,   g_v);
    cudaGetSymbolAddress((void**)&p_o,   g_o);

    cudaFuncSetAttribute(flash_mma, cudaFuncAttributeMaxDynamicSharedMemorySize, FLASH_SMEM);

    // 1) QKV projection (mma.sync tf32 3x-split, cp.async double-buffered). 33 M-tiles.
    gemm_mma<3 * CDIM><<<dim3(3 * CDIM / 128, 33), 256>>>(x, qkv_w, qkv_b, p_qkv);

    // 2) LN(q,k) + RoPE + scatter to [b][h][n][d]
    lnrope_kernel<<<dim3(NTOK, BB * NHEAD), 64>>>(p_qkv, pos_ids, tpos_ids,
                                                  qn_w, qn_b, kn_w, kn_b,
                                                  p_q, p_k, p_v);

    // 3) causal flash attention (tensor cores) -> [b][n][c]
    flash_mma<<<dim3(NTOK / 64, BB * NHEAD), 128, FLASH_SMEM>>>(p_q, p_k, p_v, p_o);

    // 4) output projection (mma.sync tf32 3x-split, cp.async double-buffered)
    gemm_mma<CDIM><<<dim3(CDIM / 128, 33), 256>>>(p_o, proj_w, proj_b, out);
}